// round 2
// baseline (speedup 1.0000x reference)
#include <cuda_runtime.h>

// Problem constants
#define Bb 4
#define Ss 2048
#define Dd 1024
#define Hh 16
#define HDim 64

// Scratch (allocation-free rule: __device__ globals; NEVER passed from host)
__device__ float g_q[Bb*Hh*Ss*HDim];     // [B,H,S,HD]
__device__ float g_k[Bb*Hh*Ss*HDim];
__device__ float g_v[Bb*Hh*Ss*HDim];
__device__ float g_attn[Bb*Ss*Dd];       // [B,S,H*HD] = [B,S,D]

#define FMA16(ACC, a, b) \
    ACC[0][0] += a.x*b.x; ACC[0][1] += a.x*b.y; ACC[0][2] += a.x*b.z; ACC[0][3] += a.x*b.w; \
    ACC[1][0] += a.y*b.x; ACC[1][1] += a.y*b.y; ACC[1][2] += a.y*b.z; ACC[1][3] += a.y*b.w; \
    ACC[2][0] += a.z*b.x; ACC[2][1] += a.z*b.y; ACC[2][2] += a.z*b.z; ACC[2][3] += a.z*b.w; \
    ACC[3][0] += a.w*b.x; ACC[3][1] += a.w*b.y; ACC[3][2] += a.w*b.z; ACC[3][3] += a.w*b.w;

// C[m,n] = sum_k A[m,k]*W[n,k] + bias[n]
// A: [M,1024] row-major, W: [1024,1024] row-major. 64 rows/block.
// mode 0: A IS g_attn (read directly in device code), write Cout row-major [M,1024]
// mode 1/2/3: A = Ain, scatter into g_q/g_k/g_v with [B,H,S,HD] layout
__global__ __launch_bounds__(256) void sgemm_kernel(
        const float* __restrict__ Ain, const float* __restrict__ W,
        const float* __restrict__ bias, float* __restrict__ Cout, int mode)
{
    __shared__ float As[16][64];
    __shared__ float Bs[16][64];
    const float* A = (mode == 0) ? (const float*)g_attn : Ain;
    const int tid = threadIdx.x;
    const int tx = tid & 15, ty = tid >> 4;
    const int bm = blockIdx.y * 64, bn = blockIdx.x * 64;
    const int lrow = tid >> 2;          // 0..63
    const int lk   = (tid & 3) << 2;    // 0,4,8,12
    const float* Ap = A + (size_t)(bm + lrow) * 1024 + lk;
    const float* Wp = W + (size_t)(bn + lrow) * 1024 + lk;

    float acc[4][4] = {};
    for (int k0 = 0; k0 < 1024; k0 += 16) {
        float4 av = *(const float4*)(Ap + k0);
        float4 wv = *(const float4*)(Wp + k0);
        __syncthreads();
        As[lk+0][lrow]=av.x; As[lk+1][lrow]=av.y; As[lk+2][lrow]=av.z; As[lk+3][lrow]=av.w;
        Bs[lk+0][lrow]=wv.x; Bs[lk+1][lrow]=wv.y; Bs[lk+2][lrow]=wv.z; Bs[lk+3][lrow]=wv.w;
        __syncthreads();
        #pragma unroll
        for (int kk = 0; kk < 16; kk++) {
            float4 a = *(const float4*)&As[kk][ty<<2];
            float4 b = *(const float4*)&Bs[kk][tx<<2];
            FMA16(acc, a, b);
        }
    }

    const int n0 = bn + (tx<<2);
    float4 bv4 = *(const float4*)&bias[n0];
    #pragma unroll
    for (int ii = 0; ii < 4; ii++) {
        const int m = bm + (ty<<2) + ii;
        float4 r;
        r.x = acc[ii][0] + bv4.x; r.y = acc[ii][1] + bv4.y;
        r.z = acc[ii][2] + bv4.z; r.w = acc[ii][3] + bv4.w;
        if (mode == 0) {
            *(float4*)&Cout[(size_t)m * 1024 + n0] = r;
        } else {
            const int b = m >> 11, s = m & (Ss-1);
            const int h = n0 >> 6, hd = n0 & 63;
            float* dst = (mode == 1) ? g_q : (mode == 2) ? g_k : g_v;
            *(float4*)&dst[(((size_t)(b*Hh + h)) * Ss + s) * HDim + hd] = r;
        }
    }
}

// In-place rotary on g_q and g_k. One thread per (tensor, b, h, s, d<32).
__global__ void rotary_kernel(const float* __restrict__ cosb, const float* __restrict__ sinb)
{
    const int half = Bb*Hh*Ss*(HDim/2);   // 4194304 per tensor
    int idx = blockIdx.x * blockDim.x + threadIdx.x;
    float* ptr = (idx < half) ? g_q : g_k;
    int i = (idx < half) ? idx : idx - half;
    const int d  = i & 31;
    const int s  = (i >> 5) & (Ss-1);
    const int bh = i >> 16;               // /(32*2048)
    const size_t off = ((size_t)bh * Ss + s) * HDim;
    float x1 = ptr[off + d], x2 = ptr[off + d + 32];
    float c1 = cosb[s*HDim + d], c2 = cosb[s*HDim + d + 32];
    float s1 = sinb[s*HDim + d], s2 = sinb[s*HDim + d + 32];
    ptr[off + d]      = x1*c1 - x2*s1;
    ptr[off + d + 32] = x2*c2 + x1*s2;
}

// Flash attention, causal. grid = (S/64, B*H). Block = 256 threads, 4x4 register tiles.
__global__ __launch_bounds__(256) void attn_kernel()
{
    __shared__ float Qs[64][64];    // [d][i]  (Q^T)
    __shared__ float KPs[64][64];   // K^T as [d][j], then reused as P^T [j][i]
    __shared__ float Vs[64][64];    // [j][hd]
    const int tid = threadIdx.x;
    const int tx = tid & 15, ty = tid >> 4;
    const int qt = blockIdx.x, bh = blockIdx.y;
    const size_t base = (size_t)bh * Ss * HDim;

    // Load Q tile transposed
    {
        const int row = tid >> 2;
        const int lk  = (tid & 3) << 2;
        const float* src = g_q + base + (size_t)(qt*64 + row) * HDim;
        #pragma unroll
        for (int dblk = 0; dblk < 4; dblk++) {
            int d0 = dblk*16 + lk;
            float4 v4 = *(const float4*)(src + d0);
            Qs[d0+0][row]=v4.x; Qs[d0+1][row]=v4.y; Qs[d0+2][row]=v4.z; Qs[d0+3][row]=v4.w;
        }
    }

    float m_i[4], l_i[4], o[4][4];
    #pragma unroll
    for (int ii = 0; ii < 4; ii++) {
        m_i[ii] = -1e30f; l_i[ii] = 0.f;
        #pragma unroll
        for (int jj = 0; jj < 4; jj++) o[ii][jj] = 0.f;
    }

    for (int kt = 0; kt <= qt; kt++) {
        __syncthreads();   // previous tile's P/V (and Q on iter 0) settled
        // Load K tile transposed + V tile natural
        {
            const int row = tid >> 2;
            const int lk  = (tid & 3) << 2;
            const float* ksrc = g_k + base + (size_t)(kt*64 + row) * HDim;
            #pragma unroll
            for (int dblk = 0; dblk < 4; dblk++) {
                int d0 = dblk*16 + lk;
                float4 v4 = *(const float4*)(ksrc + d0);
                KPs[d0+0][row]=v4.x; KPs[d0+1][row]=v4.y; KPs[d0+2][row]=v4.z; KPs[d0+3][row]=v4.w;
            }
            const float4* vsrc = (const float4*)(g_v + base + (size_t)kt*64*HDim);
            float4* vdst = (float4*)Vs;
            #pragma unroll
            for (int t = 0; t < 4; t++) vdst[tid + 256*t] = vsrc[tid + 256*t];
        }
        __syncthreads();

        // S = Q @ K^T
        float sc[4][4] = {};
        #pragma unroll 8
        for (int d = 0; d < 64; d++) {
            float4 a = *(const float4*)&Qs[d][ty<<2];
            float4 b = *(const float4*)&KPs[d][tx<<2];
            FMA16(sc, a, b);
        }
        const float scale = 0.125f;   // HD^-0.5
        if (kt == qt) {
            #pragma unroll
            for (int ii = 0; ii < 4; ii++)
                #pragma unroll
                for (int jj = 0; jj < 4; jj++) {
                    int qi = (ty<<2)+ii, kj = (tx<<2)+jj;
                    sc[ii][jj] = (kj <= qi) ? sc[ii][jj]*scale : -1e30f;
                }
        } else {
            #pragma unroll
            for (int ii = 0; ii < 4; ii++)
                #pragma unroll
                for (int jj = 0; jj < 4; jj++) sc[ii][jj] *= scale;
        }

        // Online softmax (rows live in 16-lane groups; safe within a warp)
        float fac[4];
        #pragma unroll
        for (int ii = 0; ii < 4; ii++) {
            float mt = fmaxf(fmaxf(sc[ii][0], sc[ii][1]), fmaxf(sc[ii][2], sc[ii][3]));
            #pragma unroll
            for (int off = 8; off > 0; off >>= 1)
                mt = fmaxf(mt, __shfl_xor_sync(0xffffffffu, mt, off));
            float mn = fmaxf(m_i[ii], mt);
            fac[ii] = __expf(m_i[ii] - mn);
            m_i[ii] = mn;
            float rs = 0.f;
            #pragma unroll
            for (int jj = 0; jj < 4; jj++) { sc[ii][jj] = __expf(sc[ii][jj] - mn); rs += sc[ii][jj]; }
            #pragma unroll
            for (int off = 8; off > 0; off >>= 1)
                rs += __shfl_xor_sync(0xffffffffu, rs, off);
            l_i[ii] = l_i[ii]*fac[ii] + rs;
        }

        __syncthreads();   // done reading KPs as K^T
        // Store P transposed: KPs[j][i]
        #pragma unroll
        for (int jj = 0; jj < 4; jj++)
            #pragma unroll
            for (int ii = 0; ii < 4; ii++)
                KPs[(tx<<2)+jj][(ty<<2)+ii] = sc[ii][jj];
        __syncthreads();

        // O = O*fac + P @ V
        #pragma unroll
        for (int ii = 0; ii < 4; ii++)
            #pragma unroll
            for (int jj = 0; jj < 4; jj++) o[ii][jj] *= fac[ii];
        #pragma unroll 8
        for (int j = 0; j < 64; j++) {
            float4 a = *(const float4*)&KPs[j][ty<<2];
            float4 b = *(const float4*)&Vs[j][tx<<2];
            FMA16(o, a, b);
        }
    }

    // Write [B,S,H,HD] (== [B,S,D] row-major)
    const int b = bh >> 4, h = bh & 15;
    #pragma unroll
    for (int ii = 0; ii < 4; ii++) {
        const int sq = qt*64 + (ty<<2) + ii;
        float inv = 1.f / l_i[ii];
        float4 r;
        r.x = o[ii][0]*inv; r.y = o[ii][1]*inv; r.z = o[ii][2]*inv; r.w = o[ii][3]*inv;
        *(float4*)&g_attn[(((size_t)b*Ss + sq)*Hh + h)*HDim + (tx<<2)] = r;
    }
}

extern "C" void kernel_launch(void* const* d_in, const int* in_sizes, int n_in,
                              void* d_out, int out_size)
{
    const float* x    = (const float*)d_in[0];
    const float* cosb = (const float*)d_in[1];
    const float* sinb = (const float*)d_in[2];
    // d_in[3] = attn_mask (causal, handled analytically)
    const float* Wq = (const float*)d_in[4];
    const float* bq = (const float*)d_in[5];
    const float* Wk = (const float*)d_in[6];
    const float* bk = (const float*)d_in[7];
    const float* Wv = (const float*)d_in[8];
    const float* bv = (const float*)d_in[9];
    const float* Wo = (const float*)d_in[10];
    const float* bo = (const float*)d_in[11];
    float* out = (float*)d_out;

    dim3 ggrid(Dd/64, (Bb*Ss)/64);   // (16, 128)
    sgemm_kernel<<<ggrid, 256>>>(x, Wq, bq, nullptr, 1);
    sgemm_kernel<<<ggrid, 256>>>(x, Wk, bk, nullptr, 2);
    sgemm_kernel<<<ggrid, 256>>>(x, Wv, bv, nullptr, 3);
    rotary_kernel<<<(2*Bb*Hh*Ss*(HDim/2))/256, 256>>>(cosb, sinb);
    attn_kernel<<<dim3(Ss/64, Bb*Hh), 256>>>();
    sgemm_kernel<<<ggrid, 256>>>(nullptr, Wo, bo, out, 0);   // A = g_attn (device-side)
}

// round 10
// speedup vs baseline: 1.6429x; 1.6429x over previous
#include <cuda_runtime.h>
#include <cuda_bf16.h>

// Problem constants
#define Bb 4
#define Ss 2048
#define Dd 1024
#define Hh 16
#define HDim 64
#define Mtot (Bb*Ss)   // 8192

// ---------------- scratch (__device__ globals; never passed from host) ------
__device__ float g_q[Bb*Hh*Ss*HDim];      // [B,H,S,HD]
__device__ float g_k[Bb*Hh*Ss*HDim];
__device__ float g_v[Bb*Hh*Ss*HDim];
__device__ float g_attn[Bb*Ss*Dd];        // [B,S,D]
__device__ __nv_bfloat16 g_ah[Mtot*Dd];   // activation hi/lo (x, then attn out)
__device__ __nv_bfloat16 g_al[Mtot*Dd];
__device__ __nv_bfloat16 g_wh[4*Dd*Dd];   // weights hi/lo: Wq,Wk,Wv,Wo
__device__ __nv_bfloat16 g_wl[4*Dd*Dd];

__device__ __forceinline__ unsigned smem_u32(const void* p) {
    unsigned a;
    asm("{ .reg .u64 t; cvta.to.shared.u64 t, %1; cvt.u32.u64 %0, t; }" : "=r"(a) : "l"(p));
    return a;
}

#define LDMX4(r0,r1,r2,r3,addr) \
    asm volatile("ldmatrix.sync.aligned.m8n8.x4.shared.b16 {%0,%1,%2,%3}, [%4];" \
        : "=r"(r0),"=r"(r1),"=r"(r2),"=r"(r3) : "r"(addr))

#define MMA16816(C, A, b0, b1) \
    asm volatile("mma.sync.aligned.m16n8k16.row.col.f32.bf16.bf16.f32 " \
        "{%0,%1,%2,%3}, {%4,%5,%6,%7}, {%8,%9}, {%0,%1,%2,%3};" \
        : "+f"((C)[0]),"+f"((C)[1]),"+f"((C)[2]),"+f"((C)[3]) \
        : "r"((A)[0]),"r"((A)[1]),"r"((A)[2]),"r"((A)[3]), "r"(b0),"r"(b1))

// ------------------- fp32 -> bf16 hi/lo conversion --------------------------
__global__ void conv_a_kernel(const float* __restrict__ src, int useAttn)
{
    int i = blockIdx.x * blockDim.x + threadIdx.x;   // one float4, 2M total
    const float4* s4 = useAttn ? (const float4*)g_attn : (const float4*)src;
    float4 v = s4[i];
    __nv_bfloat16 h0 = __float2bfloat16(v.x), h1 = __float2bfloat16(v.y);
    __nv_bfloat16 h2 = __float2bfloat16(v.z), h3 = __float2bfloat16(v.w);
    __nv_bfloat16 l0 = __float2bfloat16(v.x - __bfloat162float(h0));
    __nv_bfloat16 l1 = __float2bfloat16(v.y - __bfloat162float(h1));
    __nv_bfloat16 l2 = __float2bfloat16(v.z - __bfloat162float(h2));
    __nv_bfloat16 l3 = __float2bfloat16(v.w - __bfloat162float(h3));
    __nv_bfloat162* ah = (__nv_bfloat162*)g_ah;
    __nv_bfloat162* al = (__nv_bfloat162*)g_al;
    ah[2*i]   = __nv_bfloat162(h0, h1); ah[2*i+1] = __nv_bfloat162(h2, h3);
    al[2*i]   = __nv_bfloat162(l0, l1); al[2*i+1] = __nv_bfloat162(l2, l3);
}

__global__ void conv_w_kernel(const float* __restrict__ w0, const float* __restrict__ w1,
                              const float* __restrict__ w2, const float* __restrict__ w3)
{
    int widx = blockIdx.y;
    const float* w = (widx == 0) ? w0 : (widx == 1) ? w1 : (widx == 2) ? w2 : w3;
    int i = blockIdx.x * blockDim.x + threadIdx.x;   // one float4, 256K per matrix
    float4 v = ((const float4*)w)[i];
    size_t o = (size_t)widx * (Dd*Dd/2) + 2*(size_t)i;
    __nv_bfloat16 h0 = __float2bfloat16(v.x), h1 = __float2bfloat16(v.y);
    __nv_bfloat16 h2 = __float2bfloat16(v.z), h3 = __float2bfloat16(v.w);
    __nv_bfloat162* wh = (__nv_bfloat162*)g_wh;
    __nv_bfloat162* wl = (__nv_bfloat162*)g_wl;
    wh[o]   = __nv_bfloat162(h0, h1); wh[o+1] = __nv_bfloat162(h2, h3);
    wl[o]   = __nv_bfloat162(__float2bfloat16(v.x - __bfloat162float(h0)),
                             __float2bfloat16(v.y - __bfloat162float(h1)));
    wl[o+1] = __nv_bfloat162(__float2bfloat16(v.z - __bfloat162float(h2)),
                             __float2bfloat16(v.w - __bfloat162float(h3)));
}

// ------------------- mma.sync split-bf16 GEMM -------------------------------
// 128x128 CTA tile of C = A @ W^T (+bias). Terms: Ah*Wh + Al*Wh + Ah*Wl.
#define TS 40   // smem row stride in bf16 (80B, 16B-aligned, conflict-free ldmatrix)
__global__ void __launch_bounds__(256) mma_gemm_kernel(
        const float* __restrict__ bias0, const float* __restrict__ bias1,
        const float* __restrict__ bias2, float* __restrict__ Cout,
        int widxBase, int modeBase)
{
    __shared__ __nv_bfloat16 sAh[128*TS], sAl[128*TS], sWh[128*TS], sWl[128*TS];
    const int tid = threadIdx.x, wid = tid >> 5, lane = tid & 31;
    const int z = blockIdx.z;
    const int widx = widxBase + z;
    const int mode = (modeBase == 0) ? 0 : (modeBase + z);
    const float* bias = (z == 0) ? bias0 : (z == 1) ? bias1 : bias2;
    const int bm = blockIdx.y * 128, bn = blockIdx.x * 128;

    const __nv_bfloat16* Wh = g_wh + (size_t)widx * Dd * Dd;
    const __nv_bfloat16* Wl = g_wl + (size_t)widx * Dd * Dd;

    const int lrow = tid >> 1;          // 0..127
    const int lcol = (tid & 1) << 4;    // 0 or 16

    const unsigned aAh = smem_u32(sAh), aAl = smem_u32(sAl);
    const unsigned aWh = smem_u32(sWh), aWl = smem_u32(sWl);

    const int wm = (wid >> 1) * 32;
    const int wn = (wid & 1) * 64;

    float acc[2][8][4];
    #pragma unroll
    for (int i = 0; i < 2; i++)
        #pragma unroll
        for (int j = 0; j < 8; j++)
            #pragma unroll
            for (int c = 0; c < 4; c++) acc[i][j][c] = 0.f;

    uint4 pah[2], pal[2], pwh[2], pwl[2];
    #define LDG_T(kt) do { \
        const int _k = (kt)*32 + lcol; \
        const __nv_bfloat16* _a = g_ah + (size_t)(bm + lrow)*1024 + _k; \
        const __nv_bfloat16* _l = g_al + (size_t)(bm + lrow)*1024 + _k; \
        const __nv_bfloat16* _w = Wh   + (size_t)(bn + lrow)*1024 + _k; \
        const __nv_bfloat16* _x = Wl   + (size_t)(bn + lrow)*1024 + _k; \
        pah[0] = *(const uint4*)_a; pah[1] = *(const uint4*)(_a + 8); \
        pal[0] = *(const uint4*)_l; pal[1] = *(const uint4*)(_l + 8); \
        pwh[0] = *(const uint4*)_w; pwh[1] = *(const uint4*)(_w + 8); \
        pwl[0] = *(const uint4*)_x; pwl[1] = *(const uint4*)(_x + 8); \
    } while (0)

    LDG_T(0);
    for (int kt = 0; kt < 32; kt++) {
        __syncthreads();
        {
            __nv_bfloat16* d;
            d = sAh + lrow*TS + lcol; *(uint4*)d = pah[0]; *(uint4*)(d+8) = pah[1];
            d = sAl + lrow*TS + lcol; *(uint4*)d = pal[0]; *(uint4*)(d+8) = pal[1];
            d = sWh + lrow*TS + lcol; *(uint4*)d = pwh[0]; *(uint4*)(d+8) = pwh[1];
            d = sWl + lrow*TS + lcol; *(uint4*)d = pwl[0]; *(uint4*)(d+8) = pwl[1];
        }
        __syncthreads();
        if (kt < 31) LDG_T(kt + 1);

        #pragma unroll
        for (int ks = 0; ks < 2; ks++) {
            const int ro = lane & 15;
            const int co = ks*16 + ((lane >> 4) << 3);
            unsigned ah[2][4], al[2][4], bh[4][4], bl[4][4];
            #pragma unroll
            for (int mi = 0; mi < 2; mi++) {
                unsigned o = (unsigned)(((wm + mi*16 + ro)*TS + co) * 2);
                LDMX4(ah[mi][0], ah[mi][1], ah[mi][2], ah[mi][3], aAh + o);
                LDMX4(al[mi][0], al[mi][1], al[mi][2], al[mi][3], aAl + o);
            }
            #pragma unroll
            for (int nj = 0; nj < 4; nj++) {
                unsigned o = (unsigned)(((wn + nj*16 + ro)*TS + co) * 2);
                LDMX4(bh[nj][0], bh[nj][1], bh[nj][2], bh[nj][3], aWh + o);
                LDMX4(bl[nj][0], bl[nj][1], bl[nj][2], bl[nj][3], aWl + o);
            }
            #pragma unroll
            for (int mi = 0; mi < 2; mi++)
                #pragma unroll
                for (int njj = 0; njj < 8; njj++) {
                    const int nj = njj >> 1, hf = njj & 1;
                    MMA16816(acc[mi][njj], ah[mi], bh[nj][hf], bh[nj][hf+2]);
                    MMA16816(acc[mi][njj], al[mi], bh[nj][hf], bh[nj][hf+2]);
                    MMA16816(acc[mi][njj], ah[mi], bl[nj][hf], bl[nj][hf+2]);
                }
        }
    }
    #undef LDG_T

    const int erow = lane >> 2;
    const int ecol = (lane & 3) << 1;
    #pragma unroll
    for (int mi = 0; mi < 2; mi++)
        #pragma unroll
        for (int njj = 0; njj < 8; njj++) {
            const int gn = bn + wn + njj*8 + ecol;
            const float2 bv = *(const float2*)&bias[gn];
            #pragma unroll
            for (int half = 0; half < 2; half++) {
                const int gm = bm + wm + mi*16 + erow + half*8;
                float2 r;
                r.x = acc[mi][njj][half*2+0] + bv.x;
                r.y = acc[mi][njj][half*2+1] + bv.y;
                float* dst;
                if (mode == 0) {
                    dst = Cout + (size_t)gm * 1024 + gn;
                } else {
                    const int b = gm >> 11, s0 = gm & (Ss - 1);
                    const int h = gn >> 6, hd = gn & 63;
                    dst = ((mode == 1) ? g_q : (mode == 2) ? g_k : g_v)
                          + (((size_t)(b * Hh + h)) * Ss + s0) * HDim + hd;
                }
                *(float2*)dst = r;
            }
        }
}

// ------------------- rotary -------------------------------------------------
__global__ void rotary_kernel(const float* __restrict__ cosb, const float* __restrict__ sinb)
{
    const int half = Bb*Hh*Ss*(HDim/2);
    int idx = blockIdx.x * blockDim.x + threadIdx.x;
    float* ptr = (idx < half) ? g_q : g_k;
    int i = (idx < half) ? idx : idx - half;
    const int d  = i & 31;
    const int s  = (i >> 5) & (Ss-1);
    const int bh = i >> 16;
    const size_t off = ((size_t)bh * Ss + s) * HDim;
    float x1 = ptr[off + d], x2 = ptr[off + d + 32];
    float c1 = cosb[s*HDim + d], c2 = cosb[s*HDim + d + 32];
    float s1 = sinb[s*HDim + d], s2 = sinb[s*HDim + d + 32];
    ptr[off + d]      = x1*c1 - x2*s1;
    ptr[off + d + 32] = x2*c2 + x1*s2;
}

// ------------------- flash attention (fp32, proven in R2) -------------------
#define FMA16(ACC, a, b) \
    ACC[0][0] += a.x*b.x; ACC[0][1] += a.x*b.y; ACC[0][2] += a.x*b.z; ACC[0][3] += a.x*b.w; \
    ACC[1][0] += a.y*b.x; ACC[1][1] += a.y*b.y; ACC[1][2] += a.y*b.z; ACC[1][3] += a.y*b.w; \
    ACC[2][0] += a.z*b.x; ACC[2][1] += a.z*b.y; ACC[2][2] += a.z*b.z; ACC[2][3] += a.z*b.w; \
    ACC[3][0] += a.w*b.x; ACC[3][1] += a.w*b.y; ACC[3][2] += a.w*b.z; ACC[3][3] += a.w*b.w;

__global__ __launch_bounds__(256) void attn_kernel()
{
    __shared__ float Qs[64][64];
    __shared__ float KPs[64][64];
    __shared__ float Vs[64][64];
    const int tid = threadIdx.x;
    const int tx = tid & 15, ty = tid >> 4;
    const int qt = blockIdx.x, bh = blockIdx.y;
    const size_t base = (size_t)bh * Ss * HDim;

    {
        const int row = tid >> 2;
        const int lk  = (tid & 3) << 2;
        const float* src = g_q + base + (size_t)(qt*64 + row) * HDim;
        #pragma unroll
        for (int dblk = 0; dblk < 4; dblk++) {
            int d0 = dblk*16 + lk;
            float4 v4 = *(const float4*)(src + d0);
            Qs[d0+0][row]=v4.x; Qs[d0+1][row]=v4.y; Qs[d0+2][row]=v4.z; Qs[d0+3][row]=v4.w;
        }
    }

    float m_i[4], l_i[4], o[4][4];
    #pragma unroll
    for (int ii = 0; ii < 4; ii++) {
        m_i[ii] = -1e30f; l_i[ii] = 0.f;
        #pragma unroll
        for (int jj = 0; jj < 4; jj++) o[ii][jj] = 0.f;
    }

    for (int kt = 0; kt <= qt; kt++) {
        __syncthreads();
        {
            const int row = tid >> 2;
            const int lk  = (tid & 3) << 2;
            const float* ksrc = g_k + base + (size_t)(kt*64 + row) * HDim;
            #pragma unroll
            for (int dblk = 0; dblk < 4; dblk++) {
                int d0 = dblk*16 + lk;
                float4 v4 = *(const float4*)(ksrc + d0);
                KPs[d0+0][row]=v4.x; KPs[d0+1][row]=v4.y; KPs[d0+2][row]=v4.z; KPs[d0+3][row]=v4.w;
            }
            const float4* vsrc = (const float4*)(g_v + base + (size_t)kt*64*HDim);
            float4* vdst = (float4*)Vs;
            #pragma unroll
            for (int t = 0; t < 4; t++) vdst[tid + 256*t] = vsrc[tid + 256*t];
        }
        __syncthreads();

        float sc[4][4] = {};
        #pragma unroll 8
        for (int d = 0; d < 64; d++) {
            float4 a = *(const float4*)&Qs[d][ty<<2];
            float4 b = *(const float4*)&KPs[d][tx<<2];
            FMA16(sc, a, b);
        }
        const float scale = 0.125f;
        if (kt == qt) {
            #pragma unroll
            for (int ii = 0; ii < 4; ii++)
                #pragma unroll
                for (int jj = 0; jj < 4; jj++) {
                    int qi = (ty<<2)+ii, kj = (tx<<2)+jj;
                    sc[ii][jj] = (kj <= qi) ? sc[ii][jj]*scale : -1e30f;
                }
        } else {
            #pragma unroll
            for (int ii = 0; ii < 4; ii++)
                #pragma unroll
                for (int jj = 0; jj < 4; jj++) sc[ii][jj] *= scale;
        }

        float fac[4];
        #pragma unroll
        for (int ii = 0; ii < 4; ii++) {
            float mt = fmaxf(fmaxf(sc[ii][0], sc[ii][1]), fmaxf(sc[ii][2], sc[ii][3]));
            #pragma unroll
            for (int off = 8; off > 0; off >>= 1)
                mt = fmaxf(mt, __shfl_xor_sync(0xffffffffu, mt, off));
            float mn = fmaxf(m_i[ii], mt);
            fac[ii] = __expf(m_i[ii] - mn);
            m_i[ii] = mn;
            float rs = 0.f;
            #pragma unroll
            for (int jj = 0; jj < 4; jj++) { sc[ii][jj] = __expf(sc[ii][jj] - mn); rs += sc[ii][jj]; }
            #pragma unroll
            for (int off = 8; off > 0; off >>= 1)
                rs += __shfl_xor_sync(0xffffffffu, rs, off);
            l_i[ii] = l_i[ii]*fac[ii] + rs;
        }

        __syncthreads();
        #pragma unroll
        for (int jj = 0; jj < 4; jj++)
            #pragma unroll
            for (int ii = 0; ii < 4; ii++)
                KPs[(tx<<2)+jj][(ty<<2)+ii] = sc[ii][jj];
        __syncthreads();

        #pragma unroll
        for (int ii = 0; ii < 4; ii++)
            #pragma unroll
            for (int jj = 0; jj < 4; jj++) o[ii][jj] *= fac[ii];
        #pragma unroll 8
        for (int j = 0; j < 64; j++) {
            float4 a = *(const float4*)&KPs[j][ty<<2];
            float4 b = *(const float4*)&Vs[j][tx<<2];
            FMA16(o, a, b);
        }
    }

    const int b = bh >> 4, h = bh & 15;
    #pragma unroll
    for (int ii = 0; ii < 4; ii++) {
        const int sq = qt*64 + (ty<<2) + ii;
        float inv = 1.f / l_i[ii];
        float4 r;
        r.x = o[ii][0]*inv; r.y = o[ii][1]*inv; r.z = o[ii][2]*inv; r.w = o[ii][3]*inv;
        *(float4*)&g_attn[(((size_t)b*Ss + sq)*Hh + h)*HDim + (tx<<2)] = r;
    }
}

// ------------------- launcher ----------------------------------------------
extern "C" void kernel_launch(void* const* d_in, const int* in_sizes, int n_in,
                              void* d_out, int out_size)
{
    const float* x    = (const float*)d_in[0];
    const float* cosb = (const float*)d_in[1];
    const float* sinb = (const float*)d_in[2];
    // d_in[3] = attn_mask (causal, analytic)
    const float* Wq = (const float*)d_in[4];
    const float* bq = (const float*)d_in[5];
    const float* Wk = (const float*)d_in[6];
    const float* bk = (const float*)d_in[7];
    const float* Wv = (const float*)d_in[8];
    const float* bv = (const float*)d_in[9];
    const float* Wo = (const float*)d_in[10];
    const float* bo = (const float*)d_in[11];
    float* out = (float*)d_out;

    conv_a_kernel<<<(Mtot*Dd/4)/256, 256>>>(x, 0);
    conv_w_kernel<<<dim3((Dd*Dd/4)/256, 4), 256>>>(Wq, Wk, Wv, Wo);

    // fused QKV projections: z = 0,1,2 -> Wq/Wk/Wv, modes 1/2/3
    mma_gemm_kernel<<<dim3(Dd/128, Mtot/128, 3), 256>>>(bq, bk, bv, nullptr, 0, 1);

    rotary_kernel<<<(2*Bb*Hh*Ss*(HDim/2))/256, 256>>>(cosb, sinb);
    attn_kernel<<<dim3(Ss/64, Bb*Hh), 256>>>();

    conv_a_kernel<<<(Mtot*Dd/4)/256, 256>>>(nullptr, 1);
    mma_gemm_kernel<<<dim3(Dd/128, Mtot/128, 1), 256>>>(bo, nullptr, nullptr, out, 3, 0);
}

// round 12
// speedup vs baseline: 3.1857x; 1.9391x over previous
#include <cuda_runtime.h>
#include <cuda_bf16.h>
#include <cuda_fp16.h>

// Problem constants
#define Bb 4
#define Ss 2048
#define Dd 1024
#define Hh 16
#define HDim 64
#define Mtot (Bb*Ss)   // 8192

// ---------------- scratch (__device__ globals; never passed from host) ------
__device__ float g_q[Bb*Hh*Ss*HDim];      // fp32 q (pre-rotary), [B,H,S,HD]
__device__ float g_k[Bb*Hh*Ss*HDim];      // fp32 k (pre-rotary)
__device__ __half g_qh[Bb*Hh*Ss*HDim];    // fp16 q (post-rotary)
__device__ __half g_kh[Bb*Hh*Ss*HDim];    // fp16 k (post-rotary)
__device__ __half g_vh[Bb*Hh*Ss*HDim];    // fp16 v
__device__ __nv_bfloat16 g_ah[Mtot*Dd];   // activation hi/lo (x, then attn out)
__device__ __nv_bfloat16 g_al[Mtot*Dd];
__device__ __nv_bfloat16 g_wh[4*Dd*Dd];   // weights hi/lo: Wq,Wk,Wv,Wo
__device__ __nv_bfloat16 g_wl[4*Dd*Dd];

__device__ __forceinline__ unsigned smem_u32(const void* p) {
    unsigned a;
    asm("{ .reg .u64 t; cvta.to.shared.u64 t, %1; cvt.u32.u64 %0, t; }" : "=r"(a) : "l"(p));
    return a;
}

#define LDMX4(r0,r1,r2,r3,addr) \
    asm volatile("ldmatrix.sync.aligned.m8n8.x4.shared.b16 {%0,%1,%2,%3}, [%4];" \
        : "=r"(r0),"=r"(r1),"=r"(r2),"=r"(r3) : "r"(addr))
#define LDMX4T(r0,r1,r2,r3,addr) \
    asm volatile("ldmatrix.sync.aligned.m8n8.x4.trans.shared.b16 {%0,%1,%2,%3}, [%4];" \
        : "=r"(r0),"=r"(r1),"=r"(r2),"=r"(r3) : "r"(addr))

#define MMA16816(C, A, b0, b1) \
    asm volatile("mma.sync.aligned.m16n8k16.row.col.f32.bf16.bf16.f32 " \
        "{%0,%1,%2,%3}, {%4,%5,%6,%7}, {%8,%9}, {%0,%1,%2,%3};" \
        : "+f"((C)[0]),"+f"((C)[1]),"+f"((C)[2]),"+f"((C)[3]) \
        : "r"((A)[0]),"r"((A)[1]),"r"((A)[2]),"r"((A)[3]), "r"(b0),"r"(b1))
#define MMAF16(C, A, b0, b1) \
    asm volatile("mma.sync.aligned.m16n8k16.row.col.f32.f16.f16.f32 " \
        "{%0,%1,%2,%3}, {%4,%5,%6,%7}, {%8,%9}, {%0,%1,%2,%3};" \
        : "+f"((C)[0]),"+f"((C)[1]),"+f"((C)[2]),"+f"((C)[3]) \
        : "r"((A)[0]),"r"((A)[1]),"r"((A)[2]),"r"((A)[3]), "r"(b0),"r"(b1))

__device__ __forceinline__ unsigned pack_h2(float a, float b) {
    __half2 h = __floats2half2_rn(a, b);
    return *(unsigned*)&h;
}

// ------------------- fp32 -> bf16 hi/lo conversion (x only) -----------------
__global__ void conv_a_kernel(const float* __restrict__ src)
{
    int i = blockIdx.x * blockDim.x + threadIdx.x;   // one float4
    float4 v = ((const float4*)src)[i];
    __nv_bfloat16 h0 = __float2bfloat16(v.x), h1 = __float2bfloat16(v.y);
    __nv_bfloat16 h2 = __float2bfloat16(v.z), h3 = __float2bfloat16(v.w);
    __nv_bfloat162* ah = (__nv_bfloat162*)g_ah;
    __nv_bfloat162* al = (__nv_bfloat162*)g_al;
    ah[2*i]   = __nv_bfloat162(h0, h1); ah[2*i+1] = __nv_bfloat162(h2, h3);
    al[2*i]   = __nv_bfloat162(__float2bfloat16(v.x - __bfloat162float(h0)),
                               __float2bfloat16(v.y - __bfloat162float(h1)));
    al[2*i+1] = __nv_bfloat162(__float2bfloat16(v.z - __bfloat162float(h2)),
                               __float2bfloat16(v.w - __bfloat162float(h3)));
}

__global__ void conv_w_kernel(const float* __restrict__ w0, const float* __restrict__ w1,
                              const float* __restrict__ w2, const float* __restrict__ w3)
{
    int widx = blockIdx.y;
    const float* w = (widx == 0) ? w0 : (widx == 1) ? w1 : (widx == 2) ? w2 : w3;
    int i = blockIdx.x * blockDim.x + threadIdx.x;
    float4 v = ((const float4*)w)[i];
    size_t o = (size_t)widx * (Dd*Dd/2) + 2*(size_t)i;
    __nv_bfloat16 h0 = __float2bfloat16(v.x), h1 = __float2bfloat16(v.y);
    __nv_bfloat16 h2 = __float2bfloat16(v.z), h3 = __float2bfloat16(v.w);
    __nv_bfloat162* wh = (__nv_bfloat162*)g_wh;
    __nv_bfloat162* wl = (__nv_bfloat162*)g_wl;
    wh[o]   = __nv_bfloat162(h0, h1); wh[o+1] = __nv_bfloat162(h2, h3);
    wl[o]   = __nv_bfloat162(__float2bfloat16(v.x - __bfloat162float(h0)),
                             __float2bfloat16(v.y - __bfloat162float(h1)));
    wl[o+1] = __nv_bfloat162(__float2bfloat16(v.z - __bfloat162float(h2)),
                             __float2bfloat16(v.w - __bfloat162float(h3)));
}

// ------------------- mma.sync split-bf16 GEMM (proven R10) ------------------
#define TS 40
__global__ void __launch_bounds__(256) mma_gemm_kernel(
        const float* __restrict__ bias0, const float* __restrict__ bias1,
        const float* __restrict__ bias2, float* __restrict__ Cout,
        int widxBase, int modeBase)
{
    __shared__ __nv_bfloat16 sAh[128*TS], sAl[128*TS], sWh[128*TS], sWl[128*TS];
    const int tid = threadIdx.x, wid = tid >> 5, lane = tid & 31;
    const int z = blockIdx.z;
    const int widx = widxBase + z;
    const int mode = (modeBase == 0) ? 0 : (modeBase + z);
    const float* bias = (z == 0) ? bias0 : (z == 1) ? bias1 : bias2;
    const int bm = blockIdx.y * 128, bn = blockIdx.x * 128;

    const __nv_bfloat16* Wh = g_wh + (size_t)widx * Dd * Dd;
    const __nv_bfloat16* Wl = g_wl + (size_t)widx * Dd * Dd;

    const int lrow = tid >> 1;
    const int lcol = (tid & 1) << 4;

    const unsigned aAh = smem_u32(sAh), aAl = smem_u32(sAl);
    const unsigned aWh = smem_u32(sWh), aWl = smem_u32(sWl);

    const int wm = (wid >> 1) * 32;
    const int wn = (wid & 1) * 64;

    float acc[2][8][4];
    #pragma unroll
    for (int i = 0; i < 2; i++)
        #pragma unroll
        for (int j = 0; j < 8; j++)
            #pragma unroll
            for (int c = 0; c < 4; c++) acc[i][j][c] = 0.f;

    uint4 pah[2], pal[2], pwh[2], pwl[2];
    #define LDG_T(kt) do { \
        const int _k = (kt)*32 + lcol; \
        const __nv_bfloat16* _a = g_ah + (size_t)(bm + lrow)*1024 + _k; \
        const __nv_bfloat16* _l = g_al + (size_t)(bm + lrow)*1024 + _k; \
        const __nv_bfloat16* _w = Wh   + (size_t)(bn + lrow)*1024 + _k; \
        const __nv_bfloat16* _x = Wl   + (size_t)(bn + lrow)*1024 + _k; \
        pah[0] = *(const uint4*)_a; pah[1] = *(const uint4*)(_a + 8); \
        pal[0] = *(const uint4*)_l; pal[1] = *(const uint4*)(_l + 8); \
        pwh[0] = *(const uint4*)_w; pwh[1] = *(const uint4*)(_w + 8); \
        pwl[0] = *(const uint4*)_x; pwl[1] = *(const uint4*)(_x + 8); \
    } while (0)

    LDG_T(0);
    for (int kt = 0; kt < 32; kt++) {
        __syncthreads();
        {
            __nv_bfloat16* d;
            d = sAh + lrow*TS + lcol; *(uint4*)d = pah[0]; *(uint4*)(d+8) = pah[1];
            d = sAl + lrow*TS + lcol; *(uint4*)d = pal[0]; *(uint4*)(d+8) = pal[1];
            d = sWh + lrow*TS + lcol; *(uint4*)d = pwh[0]; *(uint4*)(d+8) = pwh[1];
            d = sWl + lrow*TS + lcol; *(uint4*)d = pwl[0]; *(uint4*)(d+8) = pwl[1];
        }
        __syncthreads();
        if (kt < 31) LDG_T(kt + 1);

        #pragma unroll
        for (int ks = 0; ks < 2; ks++) {
            const int ro = lane & 15;
            const int co = ks*16 + ((lane >> 4) << 3);
            unsigned ah[2][4], al[2][4], bh[4][4], bl[4][4];
            #pragma unroll
            for (int mi = 0; mi < 2; mi++) {
                unsigned o = (unsigned)(((wm + mi*16 + ro)*TS + co) * 2);
                LDMX4(ah[mi][0], ah[mi][1], ah[mi][2], ah[mi][3], aAh + o);
                LDMX4(al[mi][0], al[mi][1], al[mi][2], al[mi][3], aAl + o);
            }
            #pragma unroll
            for (int nj = 0; nj < 4; nj++) {
                unsigned o = (unsigned)(((wn + nj*16 + ro)*TS + co) * 2);
                LDMX4(bh[nj][0], bh[nj][1], bh[nj][2], bh[nj][3], aWh + o);
                LDMX4(bl[nj][0], bl[nj][1], bl[nj][2], bl[nj][3], aWl + o);
            }
            #pragma unroll
            for (int mi = 0; mi < 2; mi++)
                #pragma unroll
                for (int njj = 0; njj < 8; njj++) {
                    const int nj = njj >> 1, hf = njj & 1;
                    MMA16816(acc[mi][njj], ah[mi], bh[nj][hf], bh[nj][hf+2]);
                    MMA16816(acc[mi][njj], al[mi], bh[nj][hf], bh[nj][hf+2]);
                    MMA16816(acc[mi][njj], ah[mi], bl[nj][hf], bl[nj][hf+2]);
                }
        }
    }
    #undef LDG_T

    const int erow = lane >> 2;
    const int ecol = (lane & 3) << 1;
    #pragma unroll
    for (int mi = 0; mi < 2; mi++)
        #pragma unroll
        for (int njj = 0; njj < 8; njj++) {
            const int gn = bn + wn + njj*8 + ecol;
            const float2 bv = *(const float2*)&bias[gn];
            #pragma unroll
            for (int half = 0; half < 2; half++) {
                const int gm = bm + wm + mi*16 + erow + half*8;
                float rx = acc[mi][njj][half*2+0] + bv.x;
                float ry = acc[mi][njj][half*2+1] + bv.y;
                if (mode == 0) {
                    *(float2*)(Cout + (size_t)gm * 1024 + gn) = make_float2(rx, ry);
                } else {
                    const int b = gm >> 11, s0 = gm & (Ss - 1);
                    const int h = gn >> 6, hd = gn & 63;
                    const size_t idx = (((size_t)(b * Hh + h)) * Ss + s0) * HDim + hd;
                    if (mode == 3) {
                        *(__half2*)(g_vh + idx) = __floats2half2_rn(rx, ry);
                    } else {
                        float* dst = (mode == 1) ? g_q : g_k;
                        *(float2*)(dst + idx) = make_float2(rx, ry);
                    }
                }
            }
        }
}

// ------------------- rotary: fp32 q/k -> fp16 q/k ---------------------------
__global__ void rotary_kernel(const float* __restrict__ cosb, const float* __restrict__ sinb)
{
    const int half = Bb*Hh*Ss*(HDim/2);
    int idx = blockIdx.x * blockDim.x + threadIdx.x;
    const float* ptr = (idx < half) ? g_q : g_k;
    __half* out = (idx < half) ? g_qh : g_kh;
    int i = (idx < half) ? idx : idx - half;
    const int d  = i & 31;
    const int s  = (i >> 5) & (Ss-1);
    const int bh = i >> 16;
    const size_t off = ((size_t)bh * Ss + s) * HDim;
    float x1 = ptr[off + d], x2 = ptr[off + d + 32];
    float c1 = cosb[s*HDim + d], c2 = cosb[s*HDim + d + 32];
    float s1 = sinb[s*HDim + d], s2 = sinb[s*HDim + d + 32];
    out[off + d]      = __float2half(x1*c1 - x2*s1);
    out[off + d + 32] = __float2half(x2*c2 + x1*s2);
}

// ------------------- fp16 tensor-core flash attention -----------------------
// BQ=128, BK=64, 8 warps x 16 q-rows. Epilogue writes split-bf16 to g_ah/g_al.
#define QPAD 72
__global__ __launch_bounds__(256) void attn_f16_kernel()
{
    __shared__ __half sQ[128*QPAD];
    __shared__ __half sK[64*QPAD];
    __shared__ __half sV[64*QPAD];
    const int tid = threadIdx.x, wid = tid >> 5, lane = tid & 31;
    const int qt = blockIdx.x, bh = blockIdx.y;
    const size_t base = (size_t)bh * Ss * HDim;
    const __half* Qg = g_qh + base;
    const __half* Kg = g_kh + base;
    const __half* Vg = g_vh + base;

    // load Q tile (128 rows x 64 halves)
    {
        const int r = tid >> 1, c0 = (tid & 1) * 32;
        const uint4* src = (const uint4*)(Qg + (size_t)(qt*128 + r)*HDim + c0);
        uint4* dst = (uint4*)(sQ + r*QPAD + c0);
        #pragma unroll
        for (int j = 0; j < 4; j++) dst[j] = src[j];
    }

    // K/V prefetch (each thread: 2 uint4 per tile)
    const int kr = tid >> 2, kc = (tid & 3) * 16;
    const int nIter = 2*qt + 2;
    uint4 pk[2], pv[2];
    {
        const uint4* ks_ = (const uint4*)(Kg + (size_t)kr*HDim + kc);
        const uint4* vs_ = (const uint4*)(Vg + (size_t)kr*HDim + kc);
        pk[0]=ks_[0]; pk[1]=ks_[1]; pv[0]=vs_[0]; pv[1]=vs_[1];
    }

    __syncthreads();
    // Q fragments (held in registers for the whole kernel)
    unsigned uq[4][4];
    {
        const unsigned qa = smem_u32(sQ);
        #pragma unroll
        for (int ks = 0; ks < 4; ks++) {
            unsigned addr = qa + ((16*wid + (lane & 15))*QPAD + 16*ks + ((lane >> 4) << 3))*2;
            LDMX4(uq[ks][0], uq[ks][1], uq[ks][2], uq[ks][3], addr);
        }
    }

    float m_i[2] = {-1e30f, -1e30f}, l_i[2] = {0.f, 0.f};
    float oc[8][4];
    #pragma unroll
    for (int n = 0; n < 8; n++)
        #pragma unroll
        for (int c = 0; c < 4; c++) oc[n][c] = 0.f;

    const unsigned ka = smem_u32(sK), va = smem_u32(sV);
    const int qrow = qt*128 + wid*16 + (lane >> 2);

    for (int kt = 0; kt < nIter; kt++) {
        __syncthreads();
        {
            uint4* kd = (uint4*)(sK + kr*QPAD + kc); kd[0]=pk[0]; kd[1]=pk[1];
            uint4* vd = (uint4*)(sV + kr*QPAD + kc); vd[0]=pv[0]; vd[1]=pv[1];
        }
        __syncthreads();
        if (kt + 1 < nIter) {
            const uint4* ks_ = (const uint4*)(Kg + (size_t)((kt+1)*64 + kr)*HDim + kc);
            const uint4* vs_ = (const uint4*)(Vg + (size_t)((kt+1)*64 + kr)*HDim + kc);
            pk[0]=ks_[0]; pk[1]=ks_[1]; pv[0]=vs_[0]; pv[1]=vs_[1];
        }

        // S = Q @ K^T.  sK is [j][d] = [n][k] row-major -> NON-trans ldmatrix
        // (GEMM-proven pattern): r0=(n0-7,k0-7) r1=(n8-15,k0-7) r2=(n0-7,k8-15) r3=(n8-15,k8-15)
        float sc[8][4];
        #pragma unroll
        for (int n = 0; n < 8; n++)
            #pragma unroll
            for (int c = 0; c < 4; c++) sc[n][c] = 0.f;
        #pragma unroll
        for (int ks = 0; ks < 4; ks++) {
            #pragma unroll
            for (int np = 0; np < 4; np++) {
                unsigned b0, b1, b2, b3;
                unsigned addr = ka + ((16*np + (lane & 15))*QPAD
                                      + 16*ks + ((lane >> 4) << 3))*2;
                LDMX4(b0, b1, b2, b3, addr);
                MMAF16(sc[2*np],   uq[ks], b0, b2);
                MMAF16(sc[2*np+1], uq[ks], b1, b3);
            }
        }

        // scale + causal mask + online softmax
        const bool needmask = (kt >= 2*qt);
        const int kcol0 = kt*64 + 2*(lane & 3);
        float mrow[2] = {-1e30f, -1e30f};
        #pragma unroll
        for (int n = 0; n < 8; n++)
            #pragma unroll
            for (int c = 0; c < 4; c++) {
                float s = sc[n][c] * 0.125f;
                if (needmask) {
                    int col = kcol0 + 8*n + (c & 1);
                    int row = qrow + ((c & 2) ? 8 : 0);
                    if (col > row) s = -1e30f;
                }
                sc[n][c] = s;
                mrow[c >> 1] = fmaxf(mrow[c >> 1], s);
            }
        #pragma unroll
        for (int off = 1; off <= 2; off <<= 1) {
            mrow[0] = fmaxf(mrow[0], __shfl_xor_sync(0xffffffffu, mrow[0], off));
            mrow[1] = fmaxf(mrow[1], __shfl_xor_sync(0xffffffffu, mrow[1], off));
        }
        const float mn0 = fmaxf(m_i[0], mrow[0]);
        const float mn1 = fmaxf(m_i[1], mrow[1]);
        const float fac0 = __expf(m_i[0] - mn0);
        const float fac1 = __expf(m_i[1] - mn1);
        m_i[0] = mn0; m_i[1] = mn1;
        float rs[2] = {0.f, 0.f};
        #pragma unroll
        for (int n = 0; n < 8; n++)
            #pragma unroll
            for (int c = 0; c < 4; c++) {
                float p = __expf(sc[n][c] - ((c & 2) ? mn1 : mn0));
                sc[n][c] = p;
                rs[c >> 1] += p;
            }
        #pragma unroll
        for (int off = 1; off <= 2; off <<= 1) {
            rs[0] += __shfl_xor_sync(0xffffffffu, rs[0], off);
            rs[1] += __shfl_xor_sync(0xffffffffu, rs[1], off);
        }
        l_i[0] = l_i[0]*fac0 + rs[0];
        l_i[1] = l_i[1]*fac1 + rs[1];
        #pragma unroll
        for (int n = 0; n < 8; n++)
            #pragma unroll
            for (int c = 0; c < 4; c++) oc[n][c] *= (c & 2) ? fac1 : fac0;

        // O += P @ V.  sV is [j][d] = [k][n] row-major -> trans ldmatrix (correct)
        #pragma unroll
        for (int ks2 = 0; ks2 < 4; ks2++) {
            unsigned pa[4];
            pa[0] = pack_h2(sc[2*ks2][0],   sc[2*ks2][1]);
            pa[1] = pack_h2(sc[2*ks2][2],   sc[2*ks2][3]);
            pa[2] = pack_h2(sc[2*ks2+1][0], sc[2*ks2+1][1]);
            pa[3] = pack_h2(sc[2*ks2+1][2], sc[2*ks2+1][3]);
            #pragma unroll
            for (int np = 0; np < 4; np++) {
                unsigned b0, b1, b2, b3;
                unsigned addr = va + ((16*ks2 + (lane & 7) + ((lane & 8) ? 8 : 0))*QPAD
                                      + 16*np + ((lane & 16) ? 8 : 0))*2;
                LDMX4T(b0, b1, b2, b3, addr);
                MMAF16(oc[2*np],   pa, b0, b1);
                MMAF16(oc[2*np+1], pa, b2, b3);
            }
        }
    }

    // epilogue: normalize, split to bf16 hi/lo, write [B,S,H*HD] = [B,S,D]
    const float inv0 = 1.f / l_i[0], inv1 = 1.f / l_i[1];
    const int b = bh >> 4, h = bh & 15;
    #pragma unroll
    for (int n = 0; n < 8; n++) {
        const int hd = 8*n + 2*(lane & 3);
        #pragma unroll
        for (int half = 0; half < 2; half++) {
            const int row = qrow + half*8;
            const float vx = oc[n][half*2+0] * (half ? inv1 : inv0);
            const float vy = oc[n][half*2+1] * (half ? inv1 : inv0);
            const size_t idx = (((size_t)b*Ss + row)*Hh + h)*HDim + hd;
            __nv_bfloat16 hx = __float2bfloat16(vx), hy = __float2bfloat16(vy);
            *(__nv_bfloat162*)(g_ah + idx) = __nv_bfloat162(hx, hy);
            *(__nv_bfloat162*)(g_al + idx) =
                __nv_bfloat162(__float2bfloat16(vx - __bfloat162float(hx)),
                               __float2bfloat16(vy - __bfloat162float(hy)));
        }
    }
}

// ------------------- launcher ----------------------------------------------
extern "C" void kernel_launch(void* const* d_in, const int* in_sizes, int n_in,
                              void* d_out, int out_size)
{
    const float* x    = (const float*)d_in[0];
    const float* cosb = (const float*)d_in[1];
    const float* sinb = (const float*)d_in[2];
    // d_in[3] = attn_mask (causal, analytic)
    const float* Wq = (const float*)d_in[4];
    const float* bq = (const float*)d_in[5];
    const float* Wk = (const float*)d_in[6];
    const float* bk = (const float*)d_in[7];
    const float* Wv = (const float*)d_in[8];
    const float* bv = (const float*)d_in[9];
    const float* Wo = (const float*)d_in[10];
    const float* bo = (const float*)d_in[11];
    float* out = (float*)d_out;

    conv_a_kernel<<<(Mtot*Dd/4)/256, 256>>>(x);
    conv_w_kernel<<<dim3((Dd*Dd/4)/256, 4), 256>>>(Wq, Wk, Wv, Wo);

    // fused QKV projections: z = 0,1,2 -> Wq/Wk/Wv (q,k fp32; v fp16)
    mma_gemm_kernel<<<dim3(Dd/128, Mtot/128, 3), 256>>>(bq, bk, bv, nullptr, 0, 1);

    rotary_kernel<<<(2*Bb*Hh*Ss*(HDim/2))/256, 256>>>(cosb, sinb);

    // fp16 flash attention; writes split-bf16 activations for the final GEMM
    attn_f16_kernel<<<dim3(Ss/128, Bb*Hh), 256>>>();

    mma_gemm_kernel<<<dim3(Dd/128, Mtot/128, 1), 256>>>(bo, nullptr, nullptr, out, 3, 0);
}

// round 15
// speedup vs baseline: 5.6947x; 1.7876x over previous
#include <cuda_runtime.h>
#include <cuda_fp16.h>

// Problem constants
#define Bb 4
#define Ss 2048
#define Dd 1024
#define Hh 16
#define HDim 64
#define Mtot (Bb*Ss)   // 8192

// ---------------- scratch (__device__ globals; never passed from host) ------
__device__ float g_q[Bb*Hh*Ss*HDim];      // fp32 q (pre-rotary), [B,H,S,HD]
__device__ float g_k[Bb*Hh*Ss*HDim];      // fp32 k (pre-rotary)
__device__ __half g_qh[Bb*Hh*Ss*HDim];    // fp16 q (post-rotary)
__device__ __half g_kh[Bb*Hh*Ss*HDim];    // fp16 k (post-rotary)
__device__ __half g_vh[Bb*Hh*Ss*HDim];    // fp16 v
__device__ __half g_xh[Mtot*Dd];          // fp16 activations (x, then attn out)
__device__ __half g_wfh[4*Dd*Dd];         // fp16 weights: Wq,Wk,Wv,Wo

__device__ __forceinline__ unsigned smem_u32(const void* p) {
    unsigned a;
    asm("{ .reg .u64 t; cvta.to.shared.u64 t, %1; cvt.u32.u64 %0, t; }" : "=r"(a) : "l"(p));
    return a;
}

#define LDMX4(r0,r1,r2,r3,addr) \
    asm volatile("ldmatrix.sync.aligned.m8n8.x4.shared.b16 {%0,%1,%2,%3}, [%4];" \
        : "=r"(r0),"=r"(r1),"=r"(r2),"=r"(r3) : "r"(addr))
#define LDMX4T(r0,r1,r2,r3,addr) \
    asm volatile("ldmatrix.sync.aligned.m8n8.x4.trans.shared.b16 {%0,%1,%2,%3}, [%4];" \
        : "=r"(r0),"=r"(r1),"=r"(r2),"=r"(r3) : "r"(addr))

#define MMAF16(C, A, b0, b1) \
    asm volatile("mma.sync.aligned.m16n8k16.row.col.f32.f16.f16.f32 " \
        "{%0,%1,%2,%3}, {%4,%5,%6,%7}, {%8,%9}, {%0,%1,%2,%3};" \
        : "+f"((C)[0]),"+f"((C)[1]),"+f"((C)[2]),"+f"((C)[3]) \
        : "r"((A)[0]),"r"((A)[1]),"r"((A)[2]),"r"((A)[3]), "r"(b0),"r"(b1))

__device__ __forceinline__ unsigned pack_h2(float a, float b) {
    __half2 h = __floats2half2_rn(a, b);
    return *(unsigned*)&h;
}

// ------------------- fp32 -> fp16 conversion --------------------------------
__global__ void conv_a_kernel(const float* __restrict__ src)
{
    int i = blockIdx.x * blockDim.x + threadIdx.x;   // one float4
    float4 v = ((const float4*)src)[i];
    __half2* xh = (__half2*)g_xh;
    xh[2*i]   = __floats2half2_rn(v.x, v.y);
    xh[2*i+1] = __floats2half2_rn(v.z, v.w);
}

__global__ void conv_w_kernel(const float* __restrict__ w0, const float* __restrict__ w1,
                              const float* __restrict__ w2, const float* __restrict__ w3)
{
    int widx = blockIdx.y;
    const float* w = (widx == 0) ? w0 : (widx == 1) ? w1 : (widx == 2) ? w2 : w3;
    int i = blockIdx.x * blockDim.x + threadIdx.x;
    float4 v = ((const float4*)w)[i];
    __half2* wh = (__half2*)g_wfh;
    size_t o = (size_t)widx * (Dd*Dd/2) + 2*(size_t)i;
    wh[o]   = __floats2half2_rn(v.x, v.y);
    wh[o+1] = __floats2half2_rn(v.z, v.w);
}

// ------------------- mma.sync fp16 GEMM (single-term) -----------------------
// 128x128 CTA tile of C = A @ W^T (+bias), A fp16, W fp16, fp32 accum.
#define TS 40   // smem row stride in halves (80B, conflict-free ldmatrix)
__global__ void __launch_bounds__(256) mma_gemm_kernel(
        const float* __restrict__ bias0, const float* __restrict__ bias1,
        const float* __restrict__ bias2, float* __restrict__ Cout,
        int widxBase, int modeBase)
{
    __shared__ __half sA[128*TS], sW[128*TS];
    const int tid = threadIdx.x, wid = tid >> 5, lane = tid & 31;
    const int z = blockIdx.z;
    const int widx = widxBase + z;
    const int mode = (modeBase == 0) ? 0 : (modeBase + z);
    const float* bias = (z == 0) ? bias0 : (z == 1) ? bias1 : bias2;
    const int bm = blockIdx.y * 128, bn = blockIdx.x * 128;

    const __half* Wg = g_wfh + (size_t)widx * Dd * Dd;

    const int lrow = tid >> 1;          // 0..127
    const int lcol = (tid & 1) << 4;    // 0 or 16

    const unsigned aA = smem_u32(sA), aW = smem_u32(sW);

    const int wm = (wid >> 1) * 32;
    const int wn = (wid & 1) * 64;

    float acc[2][8][4];
    #pragma unroll
    for (int i = 0; i < 2; i++)
        #pragma unroll
        for (int j = 0; j < 8; j++)
            #pragma unroll
            for (int c = 0; c < 4; c++) acc[i][j][c] = 0.f;

    uint4 pa[2], pw[2];
    #define LDG_T(kt) do { \
        const int _k = (kt)*32 + lcol; \
        const __half* _a = g_xh + (size_t)(bm + lrow)*1024 + _k; \
        const __half* _w = Wg   + (size_t)(bn + lrow)*1024 + _k; \
        pa[0] = *(const uint4*)_a; pa[1] = *(const uint4*)(_a + 8); \
        pw[0] = *(const uint4*)_w; pw[1] = *(const uint4*)(_w + 8); \
    } while (0)

    LDG_T(0);
    for (int kt = 0; kt < 32; kt++) {
        __syncthreads();
        {
            __half* d;
            d = sA + lrow*TS + lcol; *(uint4*)d = pa[0]; *(uint4*)(d+8) = pa[1];
            d = sW + lrow*TS + lcol; *(uint4*)d = pw[0]; *(uint4*)(d+8) = pw[1];
        }
        __syncthreads();
        if (kt < 31) LDG_T(kt + 1);

        #pragma unroll
        for (int ks = 0; ks < 2; ks++) {
            const int ro = lane & 15;
            const int co = ks*16 + ((lane >> 4) << 3);
            unsigned af[2][4], bf[4][4];
            #pragma unroll
            for (int mi = 0; mi < 2; mi++) {
                unsigned o = (unsigned)(((wm + mi*16 + ro)*TS + co) * 2);
                LDMX4(af[mi][0], af[mi][1], af[mi][2], af[mi][3], aA + o);
            }
            #pragma unroll
            for (int nj = 0; nj < 4; nj++) {
                unsigned o = (unsigned)(((wn + nj*16 + ro)*TS + co) * 2);
                LDMX4(bf[nj][0], bf[nj][1], bf[nj][2], bf[nj][3], aW + o);
            }
            #pragma unroll
            for (int mi = 0; mi < 2; mi++)
                #pragma unroll
                for (int njj = 0; njj < 8; njj++) {
                    const int nj = njj >> 1, hf = njj & 1;
                    MMAF16(acc[mi][njj], af[mi], bf[nj][hf], bf[nj][hf+2]);
                }
        }
    }
    #undef LDG_T

    const int erow = lane >> 2;
    const int ecol = (lane & 3) << 1;
    #pragma unroll
    for (int mi = 0; mi < 2; mi++)
        #pragma unroll
        for (int njj = 0; njj < 8; njj++) {
            const int gn = bn + wn + njj*8 + ecol;
            const float2 bv = *(const float2*)&bias[gn];
            #pragma unroll
            for (int half = 0; half < 2; half++) {
                const int gm = bm + wm + mi*16 + erow + half*8;
                float rx = acc[mi][njj][half*2+0] + bv.x;
                float ry = acc[mi][njj][half*2+1] + bv.y;
                if (mode == 0) {
                    *(float2*)(Cout + (size_t)gm * 1024 + gn) = make_float2(rx, ry);
                } else {
                    const int b = gm >> 11, s0 = gm & (Ss - 1);
                    const int h = gn >> 6, hd = gn & 63;
                    const size_t idx = (((size_t)(b * Hh + h)) * Ss + s0) * HDim + hd;
                    if (mode == 3) {
                        *(__half2*)(g_vh + idx) = __floats2half2_rn(rx, ry);
                    } else {
                        float* dst = (mode == 1) ? g_q : g_k;
                        *(float2*)(dst + idx) = make_float2(rx, ry);
                    }
                }
            }
        }
}

// ------------------- rotary: fp32 q/k -> fp16 q/k ---------------------------
__global__ void rotary_kernel(const float* __restrict__ cosb, const float* __restrict__ sinb)
{
    const int half = Bb*Hh*Ss*(HDim/2);
    int idx = blockIdx.x * blockDim.x + threadIdx.x;
    const float* ptr = (idx < half) ? g_q : g_k;
    __half* out = (idx < half) ? g_qh : g_kh;
    int i = (idx < half) ? idx : idx - half;
    const int d  = i & 31;
    const int s  = (i >> 5) & (Ss-1);
    const int bh = i >> 16;
    const size_t off = ((size_t)bh * Ss + s) * HDim;
    float x1 = ptr[off + d], x2 = ptr[off + d + 32];
    float c1 = cosb[s*HDim + d], c2 = cosb[s*HDim + d + 32];
    float s1 = sinb[s*HDim + d], s2 = sinb[s*HDim + d + 32];
    out[off + d]      = __float2half(x1*c1 - x2*s1);
    out[off + d + 32] = __float2half(x2*c2 + x1*s2);
}

// ------------------- fp16 tensor-core flash attention (proven R12) ----------
// BQ=128, BK=64, 8 warps x 16 q-rows. Epilogue writes fp16 to g_xh.
#define QPAD 72
__global__ __launch_bounds__(256) void attn_f16_kernel()
{
    __shared__ __half sQ[128*QPAD];
    __shared__ __half sK[64*QPAD];
    __shared__ __half sV[64*QPAD];
    const int tid = threadIdx.x, wid = tid >> 5, lane = tid & 31;
    const int qt = blockIdx.x, bh = blockIdx.y;
    const size_t base = (size_t)bh * Ss * HDim;
    const __half* Qg = g_qh + base;
    const __half* Kg = g_kh + base;
    const __half* Vg = g_vh + base;

    // load Q tile (128 rows x 64 halves)
    {
        const int r = tid >> 1, c0 = (tid & 1) * 32;
        const uint4* src = (const uint4*)(Qg + (size_t)(qt*128 + r)*HDim + c0);
        uint4* dst = (uint4*)(sQ + r*QPAD + c0);
        #pragma unroll
        for (int j = 0; j < 4; j++) dst[j] = src[j];
    }

    // K/V prefetch (each thread: 2 uint4 per tile)
    const int kr = tid >> 2, kc = (tid & 3) * 16;
    const int nIter = 2*qt + 2;
    uint4 pk[2], pv[2];
    {
        const uint4* ks_ = (const uint4*)(Kg + (size_t)kr*HDim + kc);
        const uint4* vs_ = (const uint4*)(Vg + (size_t)kr*HDim + kc);
        pk[0]=ks_[0]; pk[1]=ks_[1]; pv[0]=vs_[0]; pv[1]=vs_[1];
    }

    __syncthreads();
    // Q fragments (held in registers for the whole kernel)
    unsigned uq[4][4];
    {
        const unsigned qa = smem_u32(sQ);
        #pragma unroll
        for (int ks = 0; ks < 4; ks++) {
            unsigned addr = qa + ((16*wid + (lane & 15))*QPAD + 16*ks + ((lane >> 4) << 3))*2;
            LDMX4(uq[ks][0], uq[ks][1], uq[ks][2], uq[ks][3], addr);
        }
    }

    float m_i[2] = {-1e30f, -1e30f}, l_i[2] = {0.f, 0.f};
    float oc[8][4];
    #pragma unroll
    for (int n = 0; n < 8; n++)
        #pragma unroll
        for (int c = 0; c < 4; c++) oc[n][c] = 0.f;

    const unsigned ka = smem_u32(sK), va = smem_u32(sV);
    const int qrow = qt*128 + wid*16 + (lane >> 2);

    for (int kt = 0; kt < nIter; kt++) {
        __syncthreads();
        {
            uint4* kd = (uint4*)(sK + kr*QPAD + kc); kd[0]=pk[0]; kd[1]=pk[1];
            uint4* vd = (uint4*)(sV + kr*QPAD + kc); vd[0]=pv[0]; vd[1]=pv[1];
        }
        __syncthreads();
        if (kt + 1 < nIter) {
            const uint4* ks_ = (const uint4*)(Kg + (size_t)((kt+1)*64 + kr)*HDim + kc);
            const uint4* vs_ = (const uint4*)(Vg + (size_t)((kt+1)*64 + kr)*HDim + kc);
            pk[0]=ks_[0]; pk[1]=ks_[1]; pv[0]=vs_[0]; pv[1]=vs_[1];
        }

        // S = Q @ K^T.  sK is [n][k] row-major -> non-trans ldmatrix
        float sc[8][4];
        #pragma unroll
        for (int n = 0; n < 8; n++)
            #pragma unroll
            for (int c = 0; c < 4; c++) sc[n][c] = 0.f;
        #pragma unroll
        for (int ks = 0; ks < 4; ks++) {
            #pragma unroll
            for (int np = 0; np < 4; np++) {
                unsigned b0, b1, b2, b3;
                unsigned addr = ka + ((16*np + (lane & 15))*QPAD
                                      + 16*ks + ((lane >> 4) << 3))*2;
                LDMX4(b0, b1, b2, b3, addr);
                MMAF16(sc[2*np],   uq[ks], b0, b2);
                MMAF16(sc[2*np+1], uq[ks], b1, b3);
            }
        }

        // scale + causal mask + online softmax
        const bool needmask = (kt >= 2*qt);
        const int kcol0 = kt*64 + 2*(lane & 3);
        float mrow[2] = {-1e30f, -1e30f};
        #pragma unroll
        for (int n = 0; n < 8; n++)
            #pragma unroll
            for (int c = 0; c < 4; c++) {
                float s = sc[n][c] * 0.125f;
                if (needmask) {
                    int col = kcol0 + 8*n + (c & 1);
                    int row = qrow + ((c & 2) ? 8 : 0);
                    if (col > row) s = -1e30f;
                }
                sc[n][c] = s;
                mrow[c >> 1] = fmaxf(mrow[c >> 1], s);
            }
        #pragma unroll
        for (int off = 1; off <= 2; off <<= 1) {
            mrow[0] = fmaxf(mrow[0], __shfl_xor_sync(0xffffffffu, mrow[0], off));
            mrow[1] = fmaxf(mrow[1], __shfl_xor_sync(0xffffffffu, mrow[1], off));
        }
        const float mn0 = fmaxf(m_i[0], mrow[0]);
        const float mn1 = fmaxf(m_i[1], mrow[1]);
        const float fac0 = __expf(m_i[0] - mn0);
        const float fac1 = __expf(m_i[1] - mn1);
        m_i[0] = mn0; m_i[1] = mn1;
        float rs[2] = {0.f, 0.f};
        #pragma unroll
        for (int n = 0; n < 8; n++)
            #pragma unroll
            for (int c = 0; c < 4; c++) {
                float p = __expf(sc[n][c] - ((c & 2) ? mn1 : mn0));
                sc[n][c] = p;
                rs[c >> 1] += p;
            }
        #pragma unroll
        for (int off = 1; off <= 2; off <<= 1) {
            rs[0] += __shfl_xor_sync(0xffffffffu, rs[0], off);
            rs[1] += __shfl_xor_sync(0xffffffffu, rs[1], off);
        }
        l_i[0] = l_i[0]*fac0 + rs[0];
        l_i[1] = l_i[1]*fac1 + rs[1];
        #pragma unroll
        for (int n = 0; n < 8; n++)
            #pragma unroll
            for (int c = 0; c < 4; c++) oc[n][c] *= (c & 2) ? fac1 : fac0;

        // O += P @ V.  sV is [k][n] row-major -> trans ldmatrix
        #pragma unroll
        for (int ks2 = 0; ks2 < 4; ks2++) {
            unsigned pfr[4];
            pfr[0] = pack_h2(sc[2*ks2][0],   sc[2*ks2][1]);
            pfr[1] = pack_h2(sc[2*ks2][2],   sc[2*ks2][3]);
            pfr[2] = pack_h2(sc[2*ks2+1][0], sc[2*ks2+1][1]);
            pfr[3] = pack_h2(sc[2*ks2+1][2], sc[2*ks2+1][3]);
            #pragma unroll
            for (int np = 0; np < 4; np++) {
                unsigned b0, b1, b2, b3;
                unsigned addr = va + ((16*ks2 + (lane & 7) + ((lane & 8) ? 8 : 0))*QPAD
                                      + 16*np + ((lane & 16) ? 8 : 0))*2;
                LDMX4T(b0, b1, b2, b3, addr);
                MMAF16(oc[2*np],   pfr, b0, b1);
                MMAF16(oc[2*np+1], pfr, b2, b3);
            }
        }
    }

    // epilogue: normalize, write fp16 to g_xh ([B,S,H*HD] = [B,S,D])
    const float inv0 = 1.f / l_i[0], inv1 = 1.f / l_i[1];
    const int b = bh >> 4, h = bh & 15;
    #pragma unroll
    for (int n = 0; n < 8; n++) {
        const int hd = 8*n + 2*(lane & 3);
        #pragma unroll
        for (int half = 0; half < 2; half++) {
            const int row = qrow + half*8;
            const float vx = oc[n][half*2+0] * (half ? inv1 : inv0);
            const float vy = oc[n][half*2+1] * (half ? inv1 : inv0);
            const size_t idx = (((size_t)b*Ss + row)*Hh + h)*HDim + hd;
            *(__half2*)(g_xh + idx) = __floats2half2_rn(vx, vy);
        }
    }
}

// ------------------- launcher ----------------------------------------------
extern "C" void kernel_launch(void* const* d_in, const int* in_sizes, int n_in,
                              void* d_out, int out_size)
{
    const float* x    = (const float*)d_in[0];
    const float* cosb = (const float*)d_in[1];
    const float* sinb = (const float*)d_in[2];
    // d_in[3] = attn_mask (causal, analytic)
    const float* Wq = (const float*)d_in[4];
    const float* bq = (const float*)d_in[5];
    const float* Wk = (const float*)d_in[6];
    const float* bk = (const float*)d_in[7];
    const float* Wv = (const float*)d_in[8];
    const float* bv = (const float*)d_in[9];
    const float* Wo = (const float*)d_in[10];
    const float* bo = (const float*)d_in[11];
    float* out = (float*)d_out;

    conv_a_kernel<<<(Mtot*Dd/4)/256, 256>>>(x);
    conv_w_kernel<<<dim3((Dd*Dd/4)/256, 4), 256>>>(Wq, Wk, Wv, Wo);

    // fused QKV projections: z = 0,1,2 -> Wq/Wk/Wv (q,k fp32; v fp16)
    mma_gemm_kernel<<<dim3(Dd/128, Mtot/128, 3), 256>>>(bq, bk, bv, nullptr, 0, 1);

    rotary_kernel<<<(2*Bb*Hh*Ss*(HDim/2))/256, 256>>>(cosb, sinb);

    // fp16 flash attention; writes fp16 activations for the final GEMM
    attn_f16_kernel<<<dim3(Ss/128, Bb*Hh), 256>>>();

    mma_gemm_kernel<<<dim3(Dd/128, Mtot/128, 1), 256>>>(bo, nullptr, nullptr, out, 3, 0);
}

// round 16
// speedup vs baseline: 6.2422x; 1.0961x over previous
#include <cuda_runtime.h>
#include <cuda_fp16.h>

// Problem constants
#define Bb 4
#define Ss 2048
#define Dd 1024
#define Hh 16
#define HDim 64
#define Mtot (Bb*Ss)   // 8192

// ---------------- scratch (__device__ globals; never passed from host) ------
__device__ __half g_qh[Bb*Hh*Ss*HDim];    // fp16 q (post-rotary), [B,H,S,HD]
__device__ __half g_kh[Bb*Hh*Ss*HDim];    // fp16 k (post-rotary)
__device__ __half g_vh[Bb*Hh*Ss*HDim];    // fp16 v
__device__ __half g_xh[Mtot*Dd];          // fp16 activations (x, then attn out)
__device__ __half g_wfh[4*Dd*Dd];         // fp16 weights: Wq,Wk,Wv,Wo

__device__ __forceinline__ unsigned smem_u32(const void* p) {
    unsigned a;
    asm("{ .reg .u64 t; cvta.to.shared.u64 t, %1; cvt.u32.u64 %0, t; }" : "=r"(a) : "l"(p));
    return a;
}

#define LDMX4(r0,r1,r2,r3,addr) \
    asm volatile("ldmatrix.sync.aligned.m8n8.x4.shared.b16 {%0,%1,%2,%3}, [%4];" \
        : "=r"(r0),"=r"(r1),"=r"(r2),"=r"(r3) : "r"(addr))
#define LDMX4T(r0,r1,r2,r3,addr) \
    asm volatile("ldmatrix.sync.aligned.m8n8.x4.trans.shared.b16 {%0,%1,%2,%3}, [%4];" \
        : "=r"(r0),"=r"(r1),"=r"(r2),"=r"(r3) : "r"(addr))

#define MMAF16(C, A, b0, b1) \
    asm volatile("mma.sync.aligned.m16n8k16.row.col.f32.f16.f16.f32 " \
        "{%0,%1,%2,%3}, {%4,%5,%6,%7}, {%8,%9}, {%0,%1,%2,%3};" \
        : "+f"((C)[0]),"+f"((C)[1]),"+f"((C)[2]),"+f"((C)[3]) \
        : "r"((A)[0]),"r"((A)[1]),"r"((A)[2]),"r"((A)[3]), "r"(b0),"r"(b1))

#define CPASYNC16(saddr, gptr) \
    asm volatile("cp.async.cg.shared.global [%0], [%1], 16;" :: "r"(saddr), "l"(gptr))
#define CPCOMMIT() asm volatile("cp.async.commit_group;" ::: "memory")
#define CPWAIT(N)  asm volatile("cp.async.wait_group %0;" :: "n"(N) : "memory")

__device__ __forceinline__ unsigned pack_h2(float a, float b) {
    __half2 h = __floats2half2_rn(a, b);
    return *(unsigned*)&h;
}

// ------------------- fp32 -> fp16 conversion --------------------------------
__global__ void conv_a_kernel(const float* __restrict__ src)
{
    int i = blockIdx.x * blockDim.x + threadIdx.x;
    float4 v = ((const float4*)src)[i];
    __half2* xh = (__half2*)g_xh;
    xh[2*i]   = __floats2half2_rn(v.x, v.y);
    xh[2*i+1] = __floats2half2_rn(v.z, v.w);
}

__global__ void conv_w_kernel(const float* __restrict__ w0, const float* __restrict__ w1,
                              const float* __restrict__ w2, const float* __restrict__ w3)
{
    int widx = blockIdx.y;
    const float* w = (widx == 0) ? w0 : (widx == 1) ? w1 : (widx == 2) ? w2 : w3;
    int i = blockIdx.x * blockDim.x + threadIdx.x;
    float4 v = ((const float4*)w)[i];
    __half2* wh = (__half2*)g_wfh;
    size_t o = (size_t)widx * (Dd*Dd/2) + 2*(size_t)i;
    wh[o]   = __floats2half2_rn(v.x, v.y);
    wh[o+1] = __floats2half2_rn(v.z, v.w);
}

// ------------------- cp.async double-buffered fp16 GEMM ---------------------
// 128x128 CTA tile of C = A @ W^T (+bias).
// mode 0: Cout row-major fp32. mode 1/2: fused ROTARY epilogue -> fp16 g_qh/g_kh.
// mode 3: fp16 g_vh.
#define TS 40   // smem row stride in halves
__global__ void __launch_bounds__(256) mma_gemm_kernel(
        const float* __restrict__ bias0, const float* __restrict__ bias1,
        const float* __restrict__ bias2, float* __restrict__ Cout,
        const float* __restrict__ cosb, const float* __restrict__ sinb,
        int widxBase, int modeBase)
{
    __shared__ __half sA[2][128*TS], sW[2][128*TS];
    const int tid = threadIdx.x, wid = tid >> 5, lane = tid & 31;
    const int z = blockIdx.z;
    const int widx = widxBase + z;
    const int mode = (modeBase == 0) ? 0 : (modeBase + z);
    const float* bias = (z == 0) ? bias0 : (z == 1) ? bias1 : bias2;
    const int bm = blockIdx.y * 128, bn = blockIdx.x * 128;

    const __half* Wg = g_wfh + (size_t)widx * Dd * Dd;

    const int lrow = tid >> 1;          // 0..127
    const int lcol = (tid & 1) << 4;    // 0 or 16

    unsigned aA[2] = { smem_u32(sA[0]), smem_u32(sA[1]) };
    unsigned aW[2] = { smem_u32(sW[0]), smem_u32(sW[1]) };
    const unsigned soff = (unsigned)(lrow*TS + lcol) * 2;

    const int wm = (wid >> 1) * 32;
    const int wn = (wid & 1) * 64;

    float acc[2][8][4];
    #pragma unroll
    for (int i = 0; i < 2; i++)
        #pragma unroll
        for (int j = 0; j < 8; j++)
            #pragma unroll
            for (int c = 0; c < 4; c++) acc[i][j][c] = 0.f;

    #define STAGE_LOAD(kt, st) do { \
        const int _k = (kt)*32 + lcol; \
        const __half* _a = g_xh + (size_t)(bm + lrow)*1024 + _k; \
        const __half* _w = Wg   + (size_t)(bn + lrow)*1024 + _k; \
        CPASYNC16(aA[st] + soff,      _a); \
        CPASYNC16(aA[st] + soff + 16, _a + 8); \
        CPASYNC16(aW[st] + soff,      _w); \
        CPASYNC16(aW[st] + soff + 16, _w + 8); \
    } while (0)

    STAGE_LOAD(0, 0);
    CPCOMMIT();

    for (int kt = 0; kt < 32; kt++) {
        const int st = kt & 1;
        if (kt < 31) { STAGE_LOAD(kt + 1, st ^ 1); CPCOMMIT(); CPWAIT(1); }
        else         { CPWAIT(0); }
        __syncthreads();

        #pragma unroll
        for (int ks = 0; ks < 2; ks++) {
            const int ro = lane & 15;
            const int co = ks*16 + ((lane >> 4) << 3);
            unsigned af[2][4], bf[4][4];
            #pragma unroll
            for (int mi = 0; mi < 2; mi++) {
                unsigned o = (unsigned)(((wm + mi*16 + ro)*TS + co) * 2);
                LDMX4(af[mi][0], af[mi][1], af[mi][2], af[mi][3], aA[st] + o);
            }
            #pragma unroll
            for (int nj = 0; nj < 4; nj++) {
                unsigned o = (unsigned)(((wn + nj*16 + ro)*TS + co) * 2);
                LDMX4(bf[nj][0], bf[nj][1], bf[nj][2], bf[nj][3], aW[st] + o);
            }
            #pragma unroll
            for (int mi = 0; mi < 2; mi++)
                #pragma unroll
                for (int njj = 0; njj < 8; njj++) {
                    const int nj = njj >> 1, hf = njj & 1;
                    MMAF16(acc[mi][njj], af[mi], bf[nj][hf], bf[nj][hf+2]);
                }
        }
        __syncthreads();   // compute(st) done before cp.async overwrites st next iter
    }
    #undef STAGE_LOAD

    const int erow = lane >> 2;
    const int ecol = (lane & 3) << 1;

    if (mode == 1 || mode == 2) {
        // fused rotary epilogue: thread holds col d (njj) and d+32 (njj+4)
        __half* dst = (mode == 1) ? g_qh : g_kh;
        const int h = (bn + wn) >> 6;
        #pragma unroll
        for (int mi = 0; mi < 2; mi++)
            #pragma unroll
            for (int nj = 0; nj < 4; nj++) {
                const int gn1 = bn + wn + nj*8 + ecol;   // global col, d = gn1&63 < 32
                const int d   = gn1 & 63;
                const float2 b1 = *(const float2*)&bias[gn1];
                const float2 b2 = *(const float2*)&bias[gn1 + 32];
                #pragma unroll
                for (int half = 0; half < 2; half++) {
                    const int gm = bm + wm + mi*16 + erow + half*8;
                    const int s0 = gm & (Ss - 1);
                    const int b  = gm >> 11;
                    const float x1x = acc[mi][nj][half*2+0]   + b1.x;
                    const float x1y = acc[mi][nj][half*2+1]   + b1.y;
                    const float x2x = acc[mi][nj+4][half*2+0] + b2.x;
                    const float x2y = acc[mi][nj+4][half*2+1] + b2.y;
                    const float2 c1 = *(const float2*)&cosb[s0*HDim + d];
                    const float2 s1 = *(const float2*)&sinb[s0*HDim + d];
                    const float2 c2 = *(const float2*)&cosb[s0*HDim + d + 32];
                    const float2 s2 = *(const float2*)&sinb[s0*HDim + d + 32];
                    const size_t idx = (((size_t)(b * Hh + h)) * Ss + s0) * HDim + d;
                    *(__half2*)(dst + idx) =
                        __floats2half2_rn(x1x*c1.x - x2x*s1.x, x1y*c1.y - x2y*s1.y);
                    *(__half2*)(dst + idx + 32) =
                        __floats2half2_rn(x2x*c2.x + x1x*s2.x, x2y*c2.y + x1y*s2.y);
                }
            }
    } else {
        #pragma unroll
        for (int mi = 0; mi < 2; mi++)
            #pragma unroll
            for (int njj = 0; njj < 8; njj++) {
                const int gn = bn + wn + njj*8 + ecol;
                const float2 bv = *(const float2*)&bias[gn];
                #pragma unroll
                for (int half = 0; half < 2; half++) {
                    const int gm = bm + wm + mi*16 + erow + half*8;
                    float rx = acc[mi][njj][half*2+0] + bv.x;
                    float ry = acc[mi][njj][half*2+1] + bv.y;
                    if (mode == 0) {
                        *(float2*)(Cout + (size_t)gm * 1024 + gn) = make_float2(rx, ry);
                    } else {   // mode 3: v
                        const int b = gm >> 11, s0 = gm & (Ss - 1);
                        const int h = gn >> 6, hd = gn & 63;
                        const size_t idx = (((size_t)(b * Hh + h)) * Ss + s0) * HDim + hd;
                        *(__half2*)(g_vh + idx) = __floats2half2_rn(rx, ry);
                    }
                }
            }
    }
}

// ------------------- fp16 tensor-core flash attention (proven R12/R15) ------
// BQ=128, BK=64, 8 warps x 16 q-rows. Epilogue writes fp16 to g_xh.
#define QPAD 72
__global__ __launch_bounds__(256) void attn_f16_kernel()
{
    __shared__ __half sQ[128*QPAD];
    __shared__ __half sK[64*QPAD];
    __shared__ __half sV[64*QPAD];
    const int tid = threadIdx.x, wid = tid >> 5, lane = tid & 31;
    const int qt = blockIdx.x, bh = blockIdx.y;
    const size_t base = (size_t)bh * Ss * HDim;
    const __half* Qg = g_qh + base;
    const __half* Kg = g_kh + base;
    const __half* Vg = g_vh + base;

    // load Q tile (128 rows x 64 halves)
    {
        const int r = tid >> 1, c0 = (tid & 1) * 32;
        const uint4* src = (const uint4*)(Qg + (size_t)(qt*128 + r)*HDim + c0);
        uint4* dst = (uint4*)(sQ + r*QPAD + c0);
        #pragma unroll
        for (int j = 0; j < 4; j++) dst[j] = src[j];
    }

    // K/V prefetch (each thread: 2 uint4 per tile)
    const int kr = tid >> 2, kc = (tid & 3) * 16;
    const int nIter = 2*qt + 2;
    uint4 pk[2], pv[2];
    {
        const uint4* ks_ = (const uint4*)(Kg + (size_t)kr*HDim + kc);
        const uint4* vs_ = (const uint4*)(Vg + (size_t)kr*HDim + kc);
        pk[0]=ks_[0]; pk[1]=ks_[1]; pv[0]=vs_[0]; pv[1]=vs_[1];
    }

    __syncthreads();
    unsigned uq[4][4];
    {
        const unsigned qa = smem_u32(sQ);
        #pragma unroll
        for (int ks = 0; ks < 4; ks++) {
            unsigned addr = qa + ((16*wid + (lane & 15))*QPAD + 16*ks + ((lane >> 4) << 3))*2;
            LDMX4(uq[ks][0], uq[ks][1], uq[ks][2], uq[ks][3], addr);
        }
    }

    float m_i[2] = {-1e30f, -1e30f}, l_i[2] = {0.f, 0.f};
    float oc[8][4];
    #pragma unroll
    for (int n = 0; n < 8; n++)
        #pragma unroll
        for (int c = 0; c < 4; c++) oc[n][c] = 0.f;

    const unsigned ka = smem_u32(sK), va = smem_u32(sV);
    const int qrow = qt*128 + wid*16 + (lane >> 2);

    for (int kt = 0; kt < nIter; kt++) {
        __syncthreads();
        {
            uint4* kd = (uint4*)(sK + kr*QPAD + kc); kd[0]=pk[0]; kd[1]=pk[1];
            uint4* vd = (uint4*)(sV + kr*QPAD + kc); vd[0]=pv[0]; vd[1]=pv[1];
        }
        __syncthreads();
        if (kt + 1 < nIter) {
            const uint4* ks_ = (const uint4*)(Kg + (size_t)((kt+1)*64 + kr)*HDim + kc);
            const uint4* vs_ = (const uint4*)(Vg + (size_t)((kt+1)*64 + kr)*HDim + kc);
            pk[0]=ks_[0]; pk[1]=ks_[1]; pv[0]=vs_[0]; pv[1]=vs_[1];
        }

        // S = Q @ K^T.  sK is [n][k] row-major -> non-trans ldmatrix
        float sc[8][4];
        #pragma unroll
        for (int n = 0; n < 8; n++)
            #pragma unroll
            for (int c = 0; c < 4; c++) sc[n][c] = 0.f;
        #pragma unroll
        for (int ks = 0; ks < 4; ks++) {
            #pragma unroll
            for (int np = 0; np < 4; np++) {
                unsigned b0, b1, b2, b3;
                unsigned addr = ka + ((16*np + (lane & 15))*QPAD
                                      + 16*ks + ((lane >> 4) << 3))*2;
                LDMX4(b0, b1, b2, b3, addr);
                MMAF16(sc[2*np],   uq[ks], b0, b2);
                MMAF16(sc[2*np+1], uq[ks], b1, b3);
            }
        }

        // scale + causal mask + online softmax
        const bool needmask = (kt >= 2*qt);
        const int kcol0 = kt*64 + 2*(lane & 3);
        float mrow[2] = {-1e30f, -1e30f};
        #pragma unroll
        for (int n = 0; n < 8; n++)
            #pragma unroll
            for (int c = 0; c < 4; c++) {
                float s = sc[n][c] * 0.125f;
                if (needmask) {
                    int col = kcol0 + 8*n + (c & 1);
                    int row = qrow + ((c & 2) ? 8 : 0);
                    if (col > row) s = -1e30f;
                }
                sc[n][c] = s;
                mrow[c >> 1] = fmaxf(mrow[c >> 1], s);
            }
        #pragma unroll
        for (int off = 1; off <= 2; off <<= 1) {
            mrow[0] = fmaxf(mrow[0], __shfl_xor_sync(0xffffffffu, mrow[0], off));
            mrow[1] = fmaxf(mrow[1], __shfl_xor_sync(0xffffffffu, mrow[1], off));
        }
        const float mn0 = fmaxf(m_i[0], mrow[0]);
        const float mn1 = fmaxf(m_i[1], mrow[1]);
        const float fac0 = __expf(m_i[0] - mn0);
        const float fac1 = __expf(m_i[1] - mn1);
        m_i[0] = mn0; m_i[1] = mn1;
        float rs[2] = {0.f, 0.f};
        #pragma unroll
        for (int n = 0; n < 8; n++)
            #pragma unroll
            for (int c = 0; c < 4; c++) {
                float p = __expf(sc[n][c] - ((c & 2) ? mn1 : mn0));
                sc[n][c] = p;
                rs[c >> 1] += p;
            }
        #pragma unroll
        for (int off = 1; off <= 2; off <<= 1) {
            rs[0] += __shfl_xor_sync(0xffffffffu, rs[0], off);
            rs[1] += __shfl_xor_sync(0xffffffffu, rs[1], off);
        }
        l_i[0] = l_i[0]*fac0 + rs[0];
        l_i[1] = l_i[1]*fac1 + rs[1];
        #pragma unroll
        for (int n = 0; n < 8; n++)
            #pragma unroll
            for (int c = 0; c < 4; c++) oc[n][c] *= (c & 2) ? fac1 : fac0;

        // O += P @ V.  sV is [k][n] row-major -> trans ldmatrix
        #pragma unroll
        for (int ks2 = 0; ks2 < 4; ks2++) {
            unsigned pfr[4];
            pfr[0] = pack_h2(sc[2*ks2][0],   sc[2*ks2][1]);
            pfr[1] = pack_h2(sc[2*ks2][2],   sc[2*ks2][3]);
            pfr[2] = pack_h2(sc[2*ks2+1][0], sc[2*ks2+1][1]);
            pfr[3] = pack_h2(sc[2*ks2+1][2], sc[2*ks2+1][3]);
            #pragma unroll
            for (int np = 0; np < 4; np++) {
                unsigned b0, b1, b2, b3;
                unsigned addr = va + ((16*ks2 + (lane & 7) + ((lane & 8) ? 8 : 0))*QPAD
                                      + 16*np + ((lane & 16) ? 8 : 0))*2;
                LDMX4T(b0, b1, b2, b3, addr);
                MMAF16(oc[2*np],   pfr, b0, b1);
                MMAF16(oc[2*np+1], pfr, b2, b3);
            }
        }
    }

    // epilogue: normalize, write fp16 to g_xh ([B,S,H*HD] = [B,S,D])
    const float inv0 = 1.f / l_i[0], inv1 = 1.f / l_i[1];
    const int b = bh >> 4, h = bh & 15;
    #pragma unroll
    for (int n = 0; n < 8; n++) {
        const int hd = 8*n + 2*(lane & 3);
        #pragma unroll
        for (int half = 0; half < 2; half++) {
            const int row = qrow + half*8;
            const float vx = oc[n][half*2+0] * (half ? inv1 : inv0);
            const float vy = oc[n][half*2+1] * (half ? inv1 : inv0);
            const size_t idx = (((size_t)b*Ss + row)*Hh + h)*HDim + hd;
            *(__half2*)(g_xh + idx) = __floats2half2_rn(vx, vy);
        }
    }
}

// ------------------- launcher ----------------------------------------------
extern "C" void kernel_launch(void* const* d_in, const int* in_sizes, int n_in,
                              void* d_out, int out_size)
{
    const float* x    = (const float*)d_in[0];
    const float* cosb = (const float*)d_in[1];
    const float* sinb = (const float*)d_in[2];
    // d_in[3] = attn_mask (causal, analytic)
    const float* Wq = (const float*)d_in[4];
    const float* bq = (const float*)d_in[5];
    const float* Wk = (const float*)d_in[6];
    const float* bk = (const float*)d_in[7];
    const float* Wv = (const float*)d_in[8];
    const float* bv = (const float*)d_in[9];
    const float* Wo = (const float*)d_in[10];
    const float* bo = (const float*)d_in[11];
    float* out = (float*)d_out;

    conv_a_kernel<<<(Mtot*Dd/4)/256, 256>>>(x);
    conv_w_kernel<<<dim3((Dd*Dd/4)/256, 4), 256>>>(Wq, Wk, Wv, Wo);

    // fused QKV projections: z = 0,1,2 -> Wq/Wk/Wv; rotary fused for q,k
    mma_gemm_kernel<<<dim3(Dd/128, Mtot/128, 3), 256>>>(bq, bk, bv, nullptr, cosb, sinb, 0, 1);

    // fp16 flash attention; writes fp16 activations for the final GEMM
    attn_f16_kernel<<<dim3(Ss/128, Bb*Hh), 256>>>();

    mma_gemm_kernel<<<dim3(Dd/128, Mtot/128, 1), 256>>>(bo, nullptr, nullptr, out, cosb, sinb, 3, 0);
}